// round 13
// baseline (speedup 1.0000x reference)
#include <cuda_runtime.h>
#include <cstdint>

typedef unsigned long long ull;

// Problem constants (fixed by the reference).
#define NP    16384
#define FIN   64
#define MC    4096
#define KN    64
#define FH    64
#define FO    128
#define FD    67
#define FPAD  68
#define R2F   0.04f

// Scratch (static __device__ — no allocations allowed).
__device__ int   g_idx[MC];
__device__ float g_pos_s[MC * 3];
__device__ int   g_nbr[MC * KN];
__device__ int   g_cnt[MC];
// Morton-reordered cloud: x, y, z, orig-index-bits. 256KB — L2-resident,
// and mostly L1-resident in fps (L1 = 228KB - 64KB smem).
__device__ __align__(128) float4 g_p4[NP];

// ---------------------------------------------------------------------------
// 0) Build: Morton sort (bitonic, one CTA) -> reordered float4 points.
// ---------------------------------------------------------------------------
__device__ __forceinline__ unsigned expand10(unsigned v) {
    v &= 1023u;
    v = (v | (v << 16)) & 0x030000FFu;
    v = (v | (v << 8))  & 0x0300F00Fu;
    v = (v | (v << 4))  & 0x030C30C3u;
    v = (v | (v << 2))  & 0x09249249u;
    return v;
}

#define BLD_T 512
#define BLD_SMEM (NP * 8)

__global__ __launch_bounds__(BLD_T) void build_kernel(const float* __restrict__ pos)
{
    extern __shared__ ull sk[];
    int t = threadIdx.x;

    for (int i = t; i < NP; i += BLD_T) {
        float x = pos[3 * i + 0], y = pos[3 * i + 1], z = pos[3 * i + 2];
        unsigned ux = (unsigned)fminf(1023.f, fmaxf(0.f, (x + 5.12f) * 100.0f));
        unsigned uy = (unsigned)fminf(1023.f, fmaxf(0.f, (y + 5.12f) * 100.0f));
        unsigned uz = (unsigned)fminf(1023.f, fmaxf(0.f, (z + 5.12f) * 100.0f));
        unsigned code = (expand10(ux) << 2) | (expand10(uy) << 1) | expand10(uz);
        sk[i] = ((ull)code << 32) | (unsigned)i;
    }
    __syncthreads();

    for (unsigned k2 = 2; k2 <= NP; k2 <<= 1) {
        for (unsigned j = k2 >> 1; j > 0; j >>= 1) {
            for (unsigned i = t; i < NP; i += BLD_T) {
                unsigned ixj = i ^ j;
                if (ixj > i) {
                    ull a = sk[i], b = sk[ixj];
                    bool up = ((i & k2) == 0);
                    if ((a > b) == up) { sk[i] = b; sk[ixj] = a; }
                }
            }
            __syncthreads();
        }
    }

    for (int i = t; i < NP; i += BLD_T) {
        unsigned idx = (unsigned)sk[i];
        g_p4[i] = make_float4(pos[3 * idx + 0], pos[3 * idx + 1], pos[3 * idx + 2],
                              __uint_as_float(idx));
    }
}

// ---------------------------------------------------------------------------
// 1) FPS — single persistent CTA, 512 threads / 16 warps, WARP-UNIFORM
//    chunk pruning with a statically-unrolled predicated processing loop.
//
//    512 chunks of 32 Morton-contiguous points. Warp w owns chunks
//    [32w, 32w+32); lane l keeps chunk (32w+l)'s bounding sphere, current
//    max(min_d2) bits, and cached skip-threshold in REGISTERS.
//    Per iteration:
//      A) lane l register-tests its chunk -> ballot -> warp-uniform mask.
//      B) #pragma unroll 32 slots: if (mask>>k)&1, all 32 lanes process
//         chunk k together (LDG.128 point, LDS/STS md, REDUX chunk max).
//         Skipped slots cost ~2 predicate instructions. No ffs chains,
//         back-to-back LDGs -> MLP covers L1/L2 latency.
//      C) selection: 2x REDUX + 16-entry smem; candidates re-scan via LDS;
//         exact lowest-orig tie rule via atomicMax(~orig). 3 barriers.
//    Skips are provably value-preserving -> bit-identical to dense FPS.
// ---------------------------------------------------------------------------
#define FPS_T 512
#define FPS_SMEM (NP * 4 + 128)

__global__ __launch_bounds__(FPS_T) void fps_kernel(const float* __restrict__ pos)
{
    extern __shared__ unsigned char raw[];
    float*    s_md  = (float*)raw;                     // [NP]
    unsigned* s_wm  = (unsigned*)(raw + NP * 4);       // [16]
    unsigned* s_win = s_wm + 16;                       // [2]
    float*    s_q   = (float*)(s_win + 2);             // [3]

    const int t = threadIdx.x, lane = t & 31, w = t >> 5;
    const int mychunk = (w << 5) + lane;               // chunk owned by this lane
    const float INF = __int_as_float(0x7f800000);

    for (int p = t; p < NP; p += FPS_T) s_md[p] = INF;

    // Owned chunk's bounding sphere in scalar registers.
    float ccx, ccy, ccz, crad;
    {
        float xlo = 1e30f, xhi = -1e30f, ylo = 1e30f, yhi = -1e30f,
              zlo = 1e30f, zhi = -1e30f;
        for (int m = 0; m < 32; m++) {
            float4 P = g_p4[mychunk * 32 + m];
            xlo = fminf(xlo, P.x); xhi = fmaxf(xhi, P.x);
            ylo = fminf(ylo, P.y); yhi = fmaxf(yhi, P.y);
            zlo = fminf(zlo, P.z); zhi = fmaxf(zhi, P.z);
        }
        ccx = 0.5f * (xlo + xhi); ccy = 0.5f * (ylo + yhi); ccz = 0.5f * (zlo + zhi);
        float rr = 0.0f;
        for (int m = 0; m < 32; m++) {
            float4 P = g_p4[mychunk * 32 + m];
            float dx = P.x - ccx, dy = P.y - ccy, dz = P.z - ccz;
            rr = fmaxf(rr, dx * dx + dy * dy + dz * dz);
        }
        crad = __fsqrt_ru(rr) * 1.0005f + 1e-4f;
    }
    unsigned gmax_bits = 0x7f800000u;   // owned chunk's current max(min_d2)
    float    thr2      = INF;           // cached skip threshold (INF => dirty)

    if (t == 0) {
        g_idx[0] = 0;
        s_q[0] = pos[0]; s_q[1] = pos[1]; s_q[2] = pos[2];
        s_win[0] = 0u; s_win[1] = 0u;
    }
    __syncthreads();

    for (int it = 1; it < MC; it++) {
        float qx = s_q[0], qy = s_q[1], qz = s_q[2];

        // ---- Phase A: register-only dirty test, one ballot ----
        float ddx = qx - ccx, ddy = qy - ccy, ddz = qz - ccz;
        float d2c = ddx * ddx + ddy * ddy + ddz * ddz;
        unsigned mask = __ballot_sync(0xFFFFFFFFu, d2c < thr2);

        // ---- Phase B: warp-uniform predicated processing of dirty chunks ----
#pragma unroll
        for (int k = 0; k < 32; k++) {
            if (mask & (1u << k)) {
                int p = (w << 10) + (k << 5) + lane;
                float4 P = g_p4[p];
                float dx = __fadd_rn(P.x, -qx);
                float dy = __fadd_rn(P.y, -qy);
                float dz = __fadd_rn(P.z, -qz);
                float d2 = __fmaf_rn(dz, dz, __fmaf_rn(dy, dy, __fmul_rn(dx, dx)));
                float mn = fminf(s_md[p], d2);
                s_md[p] = mn;
                unsigned gm = __reduce_max_sync(0xFFFFFFFFu, __float_as_uint(mn));
                if (lane == k) {
                    gmax_bits = gm;
                    float s = __fsqrt_ru(__uint_as_float(gm)) * 1.0005f + crad;
                    thr2 = s * s;
                }
            }
        }

        // ---- Phase C: selection (d2>=0 -> bit order == float order) ----
        unsigned wm = __reduce_max_sync(0xFFFFFFFFu, gmax_bits);
        if (lane == 0) s_wm[w] = wm;
        __syncthreads();                                  // BAR1
        unsigned v = __reduce_max_sync(0xFFFFFFFFu, s_wm[lane & 15]);
        int slot = it & 1;

        // Candidate chunks (usually exactly one in the whole block).
        unsigned cmask = __ballot_sync(0xFFFFFFFFu, gmax_bits == v);
        unsigned tinv = 0u; float tx = 0.0f, ty = 0.0f, tz = 0.0f;
        while (cmask) {
            int c = __ffs(cmask) - 1;
            cmask &= cmask - 1;
            int p = (w << 10) + (c << 5) + lane;
            bool hit = (__float_as_uint(s_md[p]) == v);
            unsigned inv = 0u;
            float4 P = make_float4(0.f, 0.f, 0.f, 0.f);
            if (hit) {
                P = g_p4[p];
                inv = ~__float_as_uint(P.w);
            }
            unsigned wi = __reduce_max_sync(0xFFFFFFFFu, inv);
            if (hit && inv == wi && wi > tinv) {
                tinv = wi; tx = P.x; ty = P.y; tz = P.z;
            }
        }
        if (tinv != 0u) atomicMax(&s_win[slot], tinv);
        if (t == 0) s_win[slot ^ 1] = 0u;
        __syncthreads();                                  // BAR2

        unsigned win = s_win[slot];
        if (tinv != 0u && tinv == win) {                  // unique winner lane
            s_q[0] = tx; s_q[1] = ty; s_q[2] = tz;
            g_idx[it] = (int)~win;
        }
        __syncthreads();                                  // BAR3
    }
}

// ---------------------------------------------------------------------------
// 2) Gather sampled positions (+ tuple tail if flattened output).
// ---------------------------------------------------------------------------
__global__ void gather_kernel(const float* __restrict__ pos, float* __restrict__ out, int out_size)
{
    int c = blockIdx.x * blockDim.x + threadIdx.x;
    if (c >= MC) return;
    int j = g_idx[c];
    float x = pos[3 * j + 0], y = pos[3 * j + 1], z = pos[3 * j + 2];
    g_pos_s[3 * c + 0] = x; g_pos_s[3 * c + 1] = y; g_pos_s[3 * c + 2] = z;
    int base = MC * FO;
    if (out_size >= base + 3 * MC) {
        out[base + 3 * c + 0] = x; out[base + 3 * c + 1] = y; out[base + 3 * c + 2] = z;
    }
    if (out_size >= base + 4 * MC) out[base + 3 * MC + c] = 0.0f;
}

// ---------------------------------------------------------------------------
// 3) Radius neighbors (unchanged, passing).
// ---------------------------------------------------------------------------
#define RB_C   16
#define RB_T   256
#define RB_CAP 192

__global__ __launch_bounds__(RB_T) void radius_kernel(const float* __restrict__ pos)
{
    __shared__ float scx[RB_C], scy[RB_C], scz[RB_C];
    __shared__ int   scnt[RB_C];
    __shared__ int   sidx[RB_C][RB_CAP];
    __shared__ float sd2[RB_C][RB_CAP];

    int t = threadIdx.x;
    int c0 = blockIdx.x * RB_C;
    if (t < RB_C) {
        scx[t] = g_pos_s[3 * (c0 + t) + 0];
        scy[t] = g_pos_s[3 * (c0 + t) + 1];
        scz[t] = g_pos_s[3 * (c0 + t) + 2];
        scnt[t] = 0;
    }
    __syncthreads();

    for (int j = t; j < NP; j += RB_T) {
        float x = pos[3 * j + 0], y = pos[3 * j + 1], z = pos[3 * j + 2];
#pragma unroll
        for (int c = 0; c < RB_C; c++) {
            float dx = __fadd_rn(scx[c], -x);
            float dy = __fadd_rn(scy[c], -y);
            float dz = __fadd_rn(scz[c], -z);
            float d2 = __fmaf_rn(dz, dz, __fmaf_rn(dy, dy, __fmul_rn(dx, dx)));
            if (d2 <= R2F) {
                int n = atomicAdd(&scnt[c], 1);
                if (n < RB_CAP) { sidx[c][n] = j; sd2[c][n] = d2; }
            }
        }
    }
    __syncthreads();

    for (int c = 0; c < RB_C; c++) {
        int cnt = min(scnt[c], RB_CAP);
        int cg = c0 + c;
        if (cnt <= KN) {
            if (t < cnt) g_nbr[cg * KN + t] = sidx[c][t];
            if (t == 0)  g_cnt[cg] = cnt;
        } else {
            for (int i = t; i < cnt; i += RB_T) {
                float di = sd2[c][i]; int ii = sidx[c][i];
                int rank = 0;
                for (int jj = 0; jj < cnt; jj++) {
                    float dj = sd2[c][jj];
                    rank += (dj < di) || (dj == di && sidx[c][jj] < ii);
                }
                if (rank < KN) g_nbr[cg * KN + rank] = ii;
            }
            if (t == 0) g_cnt[cg] = KN;
        }
    }
}

// ---------------------------------------------------------------------------
// 4) Per-edge MLP + max-pool (unchanged, passing).
// ---------------------------------------------------------------------------
#define ML_T    256
#define ML_GRID 304

#define OFF_W1 0
#define OFF_W2 (OFF_W1 + FD * FH)
#define OFF_W3 (OFF_W2 + FH * FH)
#define OFF_B1 (OFF_W3 + FH * FO)
#define OFF_B2 (OFF_B1 + FH)
#define OFF_B3 (OFF_B2 + FH)
#define OFF_F  (OFF_B3 + FO)
#define OFF_H  (OFF_F + KN * FPAD)
#define OFF_O  (OFF_H + KN * FPAD)
#define ML_SMEM ((OFF_O + FO) * 4)

__global__ __launch_bounds__(ML_T, 2) void mlp_kernel(
    const float* __restrict__ x, const float* __restrict__ pos,
    const float* __restrict__ W1, const float* __restrict__ b1,
    const float* __restrict__ W2, const float* __restrict__ b2,
    const float* __restrict__ W3, const float* __restrict__ b3,
    float* __restrict__ out)
{
    extern __shared__ float sm[];
    float* sW1 = sm + OFF_W1;
    float* sW2 = sm + OFF_W2;
    float* sW3 = sm + OFF_W3;
    float* sb1 = sm + OFF_B1;
    float* sb2 = sm + OFF_B2;
    float* sb3 = sm + OFF_B3;
    float* sF  = sm + OFF_F;
    float* sH  = sm + OFF_H;
    int*   sO  = (int*)(sm + OFF_O);

    int t = threadIdx.x;
    for (int i = t; i < FD * FH; i += ML_T) sW1[i] = W1[i];
    for (int i = t; i < FH * FH; i += ML_T) sW2[i] = W2[i];
    for (int i = t; i < FH * FO; i += ML_T) sW3[i] = W3[i];
    if (t < FH) { sb1[t] = b1[t]; sb2[t] = b2[t]; }
    if (t < FO) sb3[t] = b3[t];

    int ei = t >> 4, ci = t & 15;

    for (int c = blockIdx.x; c < MC; c += gridDim.x) {
        __syncthreads();
        if (t < FO) sO[t] = 0;
        int E = g_cnt[c];
        float cx = g_pos_s[3 * c + 0], cy = g_pos_s[3 * c + 1], cz = g_pos_s[3 * c + 2];

        {
            int e = t >> 2, q = t & 3;
            if (e < E) {
                int nb = g_nbr[c * KN + e];
                const float4* xr = (const float4*)(x + (size_t)nb * FIN);
                float4* dst = (float4*)(sF + e * FPAD + q * 16);
                dst[0] = xr[q * 4 + 0]; dst[1] = xr[q * 4 + 1];
                dst[2] = xr[q * 4 + 2]; dst[3] = xr[q * 4 + 3];
                if (q == 0) {
                    sF[e * FPAD + 64] = pos[3 * nb + 0] - cx;
                    sF[e * FPAD + 65] = pos[3 * nb + 1] - cy;
                    sF[e * FPAD + 66] = pos[3 * nb + 2] - cz;
                    sF[e * FPAD + 67] = 0.0f;
                }
            }
        }
        __syncthreads();
        int ET = (E + 3) >> 2;

        if (ei < ET) {
            float acc[4][4];
#pragma unroll
            for (int j = 0; j < 4; j++)
#pragma unroll
                for (int a = 0; a < 4; a++) acc[j][a] = sb1[ci * 4 + a];
#pragma unroll 4
            for (int k = 0; k < FD; k++) {
                float4 wv = *(const float4*)(sW1 + k * FH + ci * 4);
                float f[4];
#pragma unroll
                for (int j = 0; j < 4; j++) f[j] = sF[(4 * ei + j) * FPAD + k];
#pragma unroll
                for (int j = 0; j < 4; j++) {
                    acc[j][0] += f[j] * wv.x; acc[j][1] += f[j] * wv.y;
                    acc[j][2] += f[j] * wv.z; acc[j][3] += f[j] * wv.w;
                }
            }
#pragma unroll
            for (int j = 0; j < 4; j++)
#pragma unroll
                for (int a = 0; a < 4; a++)
                    sH[(4 * ei + j) * FPAD + ci * 4 + a] = fmaxf(acc[j][a], 0.0f);
        }
        __syncthreads();

        if (ei < ET) {
            float acc[4][4];
#pragma unroll
            for (int j = 0; j < 4; j++)
#pragma unroll
                for (int a = 0; a < 4; a++) acc[j][a] = sb2[ci * 4 + a];
#pragma unroll 4
            for (int k = 0; k < FH; k++) {
                float4 wv = *(const float4*)(sW2 + k * FH + ci * 4);
                float f[4];
#pragma unroll
                for (int j = 0; j < 4; j++) f[j] = sH[(4 * ei + j) * FPAD + k];
#pragma unroll
                for (int j = 0; j < 4; j++) {
                    acc[j][0] += f[j] * wv.x; acc[j][1] += f[j] * wv.y;
                    acc[j][2] += f[j] * wv.z; acc[j][3] += f[j] * wv.w;
                }
            }
#pragma unroll
            for (int j = 0; j < 4; j++)
#pragma unroll
                for (int a = 0; a < 4; a++)
                    sF[(4 * ei + j) * FPAD + ci * 4 + a] = fmaxf(acc[j][a], 0.0f);
        }
        __syncthreads();

        if (ei < ET) {
            float acc[4][8];
#pragma unroll
            for (int j = 0; j < 4; j++)
#pragma unroll
                for (int a = 0; a < 8; a++) acc[j][a] = sb3[ci * 8 + a];
#pragma unroll 4
            for (int k = 0; k < FH; k++) {
                float4 wa = *(const float4*)(sW3 + k * FO + ci * 8);
                float4 wb = *(const float4*)(sW3 + k * FO + ci * 8 + 4);
                float f[4];
#pragma unroll
                for (int j = 0; j < 4; j++) f[j] = sF[(4 * ei + j) * FPAD + k];
#pragma unroll
                for (int j = 0; j < 4; j++) {
                    acc[j][0] += f[j] * wa.x; acc[j][1] += f[j] * wa.y;
                    acc[j][2] += f[j] * wa.z; acc[j][3] += f[j] * wa.w;
                    acc[j][4] += f[j] * wb.x; acc[j][5] += f[j] * wb.y;
                    acc[j][6] += f[j] * wb.z; acc[j][7] += f[j] * wb.w;
                }
            }
#pragma unroll
            for (int a = 0; a < 8; a++) {
                float mv = -1.0f;
#pragma unroll
                for (int j = 0; j < 4; j++)
                    if (4 * ei + j < E) mv = fmaxf(mv, fmaxf(acc[j][a], 0.0f));
                if (mv >= 0.0f) atomicMax(&sO[ci * 8 + a], __float_as_int(mv));
            }
        }
        __syncthreads();
        if (t < FO) out[(size_t)c * FO + t] = __int_as_float(sO[t]);
    }
}

// ---------------------------------------------------------------------------
extern "C" void kernel_launch(void* const* d_in, const int* in_sizes, int n_in,
                              void* d_out, int out_size)
{
    const float* x   = (const float*)d_in[0];
    const float* pos = (const float*)d_in[1];
    const float* W1 = (const float*)d_in[3];
    const float* b1 = (const float*)d_in[4];
    const float* W2 = (const float*)d_in[5];
    const float* b2 = (const float*)d_in[6];
    const float* W3 = (const float*)d_in[7];
    const float* b3 = (const float*)d_in[8];
    float* out = (float*)d_out;

    cudaFuncSetAttribute(build_kernel, cudaFuncAttributeMaxDynamicSharedMemorySize, BLD_SMEM);
    cudaFuncSetAttribute(fps_kernel,   cudaFuncAttributeMaxDynamicSharedMemorySize, FPS_SMEM);
    cudaFuncSetAttribute(mlp_kernel,   cudaFuncAttributeMaxDynamicSharedMemorySize, ML_SMEM);

    build_kernel<<<1, BLD_T, BLD_SMEM>>>(pos);
    fps_kernel<<<1, FPS_T, FPS_SMEM>>>(pos);
    gather_kernel<<<(MC + 255) / 256, 256>>>(pos, out, out_size);
    radius_kernel<<<MC / RB_C, RB_T>>>(pos);
    mlp_kernel<<<ML_GRID, ML_T, ML_SMEM>>>(x, pos, W1, b1, W2, b2, W3, b3, out);
}

// round 14
// speedup vs baseline: 1.8197x; 1.8197x over previous
#include <cuda_runtime.h>
#include <cstdint>

typedef unsigned long long ull;

// Problem constants (fixed by the reference).
#define NP    16384
#define FIN   64
#define MC    4096
#define KN    64
#define FH    64
#define FO    128
#define FD    67
#define FPAD  68
#define R2F   0.04f

// Scratch (static __device__ — no allocations allowed).
__device__ int   g_idx[MC];
__device__ float g_pos_s[MC * 3];
__device__ int   g_nbr[MC * KN];
__device__ int   g_cnt[MC];
// Morton-reordered cloud
__device__ __align__(128) float g_px[NP];
__device__ __align__(128) float g_py[NP];
__device__ __align__(128) float g_pz[NP];
__device__ __align__(128) int   g_orig[NP];

// Packed f32x2 helpers (sm_103a): per-lane IEEE rn — bit-identical to scalar.
#define PACK2(out, lo, hi)  asm("mov.b64 %0, {%1, %2};" : "=l"(out) : "f"(lo), "f"(hi))
#define UNPACK2(lo, hi, in) asm("mov.b64 {%0, %1}, %2;" : "=f"(lo), "=f"(hi) : "l"(in))
#define ADD2(out, a, b)     asm("add.rn.f32x2 %0, %1, %2;" : "=l"(out) : "l"(a), "l"(b))
#define MUL2(out, a, b)     asm("mul.rn.f32x2 %0, %1, %2;" : "=l"(out) : "l"(a), "l"(b))
#define FMA2(out, a, b, c)  asm("fma.rn.f32x2 %0, %1, %2, %3;" : "=l"(out) : "l"(a), "l"(b), "l"(c))

// ---------------------------------------------------------------------------
// 0) Build: Morton sort (bitonic, one CTA) -> reordered coords.
// ---------------------------------------------------------------------------
__device__ __forceinline__ unsigned expand10(unsigned v) {
    v &= 1023u;
    v = (v | (v << 16)) & 0x030000FFu;
    v = (v | (v << 8))  & 0x0300F00Fu;
    v = (v | (v << 4))  & 0x030C30C3u;
    v = (v | (v << 2))  & 0x09249249u;
    return v;
}

#define BLD_T 512
#define BLD_SMEM (NP * 8)

__global__ __launch_bounds__(BLD_T) void build_kernel(const float* __restrict__ pos)
{
    extern __shared__ ull sk[];
    int t = threadIdx.x;

    for (int i = t; i < NP; i += BLD_T) {
        float x = pos[3 * i + 0], y = pos[3 * i + 1], z = pos[3 * i + 2];
        unsigned ux = (unsigned)fminf(1023.f, fmaxf(0.f, (x + 5.12f) * 100.0f));
        unsigned uy = (unsigned)fminf(1023.f, fmaxf(0.f, (y + 5.12f) * 100.0f));
        unsigned uz = (unsigned)fminf(1023.f, fmaxf(0.f, (z + 5.12f) * 100.0f));
        unsigned code = (expand10(ux) << 2) | (expand10(uy) << 1) | expand10(uz);
        sk[i] = ((ull)code << 32) | (unsigned)i;
    }
    __syncthreads();

    for (unsigned k2 = 2; k2 <= NP; k2 <<= 1) {
        for (unsigned j = k2 >> 1; j > 0; j >>= 1) {
            for (unsigned i = t; i < NP; i += BLD_T) {
                unsigned ixj = i ^ j;
                if (ixj > i) {
                    ull a = sk[i], b = sk[ixj];
                    bool up = ((i & k2) == 0);
                    if ((a > b) == up) { sk[i] = b; sk[ixj] = a; }
                }
            }
            __syncthreads();
        }
    }

    for (int i = t; i < NP; i += BLD_T) {
        unsigned idx = (unsigned)sk[i];
        g_px[i] = pos[3 * idx + 0];
        g_py[i] = pos[3 * idx + 1];
        g_pz[i] = pos[3 * idx + 2];
        g_orig[i] = (int)idx;
    }
}

// ---------------------------------------------------------------------------
// 1) FPS — single persistent CTA, 512 threads, DENSE (13 rounds of evidence:
//    every pruning structure lost to the plain SIMT loop on this workload).
//    Thread t owns points [32t, 32t+32):
//      x,y pairs + md in REGISTERS (96 persistent regs, static indexing only),
//      z pairs in smem (one LDS.64 per pair -> 64KB crossbar per iteration,
//      half of R10's), orig as u16 in smem (candidate path only).
//    Inner loop: ~11 inst/pair of packed f32x2 math, bit-identical to the
//    reference's fused scalar d2. Selection: 2 REDUX + 3 barriers (R10's).
// ---------------------------------------------------------------------------
#define FPS_T 512
#define OZ2   0
#define OOR   (OZ2 + (NP / 2) * 8)
#define OMISC (OOR + NP * 2)
#define FPS_SMEM (OMISC + 128)

__global__ __launch_bounds__(FPS_T) void fps_kernel(const float* __restrict__ pos)
{
    extern __shared__ unsigned char raw[];
    float2*         s_z2  = (float2*)(raw + OZ2);          // [NP/2] (z0,z1) pairs
    unsigned short* s_or  = (unsigned short*)(raw + OOR);  // [NP] transposed
    unsigned*       s_wm  = (unsigned*)(raw + OMISC);      // [16]
    unsigned*       s_win = s_wm + 16;                     // [2]
    float*          s_q   = (float*)(s_win + 2);           // [3]

    const int t = threadIdx.x, lane = t & 31, w = t >> 5;
    const int base = t * 32;
    const float INF = __int_as_float(0x7f800000);

    ull   px2[16], py2[16];
    float md[32];
#pragma unroll
    for (int i = 0; i < 16; i++) {
        int p = base + 2 * i;
        float x0 = g_px[p], x1 = g_px[p + 1];
        float y0 = g_py[p], y1 = g_py[p + 1];
        PACK2(px2[i], x0, x1);
        PACK2(py2[i], y0, y1);
        s_z2[i * FPS_T + t] = make_float2(g_pz[p], g_pz[p + 1]);
        s_or[(2 * i) * FPS_T + t]     = (unsigned short)g_orig[p];
        s_or[(2 * i + 1) * FPS_T + t] = (unsigned short)g_orig[p + 1];
        md[2 * i] = INF; md[2 * i + 1] = INF;
    }

    if (t == 0) {
        g_idx[0] = 0;
        s_q[0] = pos[0]; s_q[1] = pos[1]; s_q[2] = pos[2];
        s_win[0] = 0u; s_win[1] = 0u;
    }
    __syncthreads();

    for (int it = 1; it < MC; it++) {
        float qx = s_q[0], qy = s_q[1], qz = s_q[2];
        ull qx2, qy2, qz2;
        {
            float nqx = -qx, nqy = -qy, nqz = -qz;
            PACK2(qx2, nqx, nqx); PACK2(qy2, nqy, nqy); PACK2(qz2, nqz, nqz);
        }

        // ---- Dense update: 16 packed pairs, x/y/md register-resident ----
        float best = -1.0f;
#pragma unroll
        for (int i = 0; i < 16; i++) {
            float2 z2 = s_z2[i * FPS_T + t];
            ull pz2, dx2, dy2, dz2, s1, d2p;
            PACK2(pz2, z2.x, z2.y);
            ADD2(dx2, px2[i], qx2);            // x - qx (rn, per lane)
            ADD2(dy2, py2[i], qy2);
            ADD2(dz2, pz2, qz2);
            MUL2(s1, dx2, dx2);                // dx*dx
            FMA2(s1, dy2, dy2, s1);            // fma(dy,dy,.)
            FMA2(d2p, dz2, dz2, s1);           // fma(dz,dz,.)
            float d2a, d2b; UNPACK2(d2a, d2b, d2p);
            float m0 = fminf(md[2 * i], d2a);
            float m1 = fminf(md[2 * i + 1], d2b);
            md[2 * i] = m0; md[2 * i + 1] = m1;
            best = fmaxf(best, fmaxf(m0, m1));
        }

        // ---- Selection (R10's proven path): 2 REDUX + 3 barriers ----
        unsigned lb = __float_as_uint(best);       // d2>=0: bit order == float order
        unsigned wm = __reduce_max_sync(0xFFFFFFFFu, lb);
        if (lane == 0) s_wm[w] = wm;
        __syncthreads();                                  // BAR1
        unsigned v = __reduce_max_sync(0xFFFFFFFFu, s_wm[lane & 15]);
        int slot = it & 1;

        unsigned tinv = 0u; float tx = 0.0f, ty = 0.0f, tz = 0.0f;
        if (lb == v) {                                    // candidate thread(s)
#pragma unroll
            for (int m = 0; m < 32; m++) {
                if (__float_as_uint(md[m]) == v) {
                    unsigned inv = 0xFFFFFFFFu - (unsigned)s_or[m * FPS_T + t];
                    if (inv > tinv) {
                        tinv = inv;
                        float a, b;
                        UNPACK2(a, b, px2[m >> 1]);
                        tx = (m & 1) ? b : a;
                        UNPACK2(a, b, py2[m >> 1]);
                        ty = (m & 1) ? b : a;
                        float2 z2 = s_z2[(m >> 1) * FPS_T + t];
                        tz = (m & 1) ? z2.y : z2.x;
                    }
                }
            }
            atomicMax(&s_win[slot], tinv);
        }
        if (t == 0) s_win[slot ^ 1] = 0u;
        __syncthreads();                                  // BAR2

        unsigned win = s_win[slot];
        if (tinv != 0u && tinv == win) {                  // unique winner thread
            s_q[0] = tx; s_q[1] = ty; s_q[2] = tz;
            g_idx[it] = (int)(0xFFFFFFFFu - win);
        }
        __syncthreads();                                  // BAR3
    }
}

// ---------------------------------------------------------------------------
// 2) Gather sampled positions (+ tuple tail if flattened output).
// ---------------------------------------------------------------------------
__global__ void gather_kernel(const float* __restrict__ pos, float* __restrict__ out, int out_size)
{
    int c = blockIdx.x * blockDim.x + threadIdx.x;
    if (c >= MC) return;
    int j = g_idx[c];
    float x = pos[3 * j + 0], y = pos[3 * j + 1], z = pos[3 * j + 2];
    g_pos_s[3 * c + 0] = x; g_pos_s[3 * c + 1] = y; g_pos_s[3 * c + 2] = z;
    int base = MC * FO;
    if (out_size >= base + 3 * MC) {
        out[base + 3 * c + 0] = x; out[base + 3 * c + 1] = y; out[base + 3 * c + 2] = z;
    }
    if (out_size >= base + 4 * MC) out[base + 3 * MC + c] = 0.0f;
}

// ---------------------------------------------------------------------------
// 3) Radius neighbors (unchanged, passing).
// ---------------------------------------------------------------------------
#define RB_C   16
#define RB_T   256
#define RB_CAP 192

__global__ __launch_bounds__(RB_T) void radius_kernel(const float* __restrict__ pos)
{
    __shared__ float scx[RB_C], scy[RB_C], scz[RB_C];
    __shared__ int   scnt[RB_C];
    __shared__ int   sidx[RB_C][RB_CAP];
    __shared__ float sd2[RB_C][RB_CAP];

    int t = threadIdx.x;
    int c0 = blockIdx.x * RB_C;
    if (t < RB_C) {
        scx[t] = g_pos_s[3 * (c0 + t) + 0];
        scy[t] = g_pos_s[3 * (c0 + t) + 1];
        scz[t] = g_pos_s[3 * (c0 + t) + 2];
        scnt[t] = 0;
    }
    __syncthreads();

    for (int j = t; j < NP; j += RB_T) {
        float x = pos[3 * j + 0], y = pos[3 * j + 1], z = pos[3 * j + 2];
#pragma unroll
        for (int c = 0; c < RB_C; c++) {
            float dx = __fadd_rn(scx[c], -x);
            float dy = __fadd_rn(scy[c], -y);
            float dz = __fadd_rn(scz[c], -z);
            float d2 = __fmaf_rn(dz, dz, __fmaf_rn(dy, dy, __fmul_rn(dx, dx)));
            if (d2 <= R2F) {
                int n = atomicAdd(&scnt[c], 1);
                if (n < RB_CAP) { sidx[c][n] = j; sd2[c][n] = d2; }
            }
        }
    }
    __syncthreads();

    for (int c = 0; c < RB_C; c++) {
        int cnt = min(scnt[c], RB_CAP);
        int cg = c0 + c;
        if (cnt <= KN) {
            if (t < cnt) g_nbr[cg * KN + t] = sidx[c][t];
            if (t == 0)  g_cnt[cg] = cnt;
        } else {
            for (int i = t; i < cnt; i += RB_T) {
                float di = sd2[c][i]; int ii = sidx[c][i];
                int rank = 0;
                for (int jj = 0; jj < cnt; jj++) {
                    float dj = sd2[c][jj];
                    rank += (dj < di) || (dj == di && sidx[c][jj] < ii);
                }
                if (rank < KN) g_nbr[cg * KN + rank] = ii;
            }
            if (t == 0) g_cnt[cg] = KN;
        }
    }
}

// ---------------------------------------------------------------------------
// 4) Per-edge MLP + max-pool (unchanged, passing).
// ---------------------------------------------------------------------------
#define ML_T    256
#define ML_GRID 304

#define OFF_W1 0
#define OFF_W2 (OFF_W1 + FD * FH)
#define OFF_W3 (OFF_W2 + FH * FH)
#define OFF_B1 (OFF_W3 + FH * FO)
#define OFF_B2 (OFF_B1 + FH)
#define OFF_B3 (OFF_B2 + FH)
#define OFF_F  (OFF_B3 + FO)
#define OFF_H  (OFF_F + KN * FPAD)
#define OFF_O  (OFF_H + KN * FPAD)
#define ML_SMEM ((OFF_O + FO) * 4)

__global__ __launch_bounds__(ML_T, 2) void mlp_kernel(
    const float* __restrict__ x, const float* __restrict__ pos,
    const float* __restrict__ W1, const float* __restrict__ b1,
    const float* __restrict__ W2, const float* __restrict__ b2,
    const float* __restrict__ W3, const float* __restrict__ b3,
    float* __restrict__ out)
{
    extern __shared__ float sm[];
    float* sW1 = sm + OFF_W1;
    float* sW2 = sm + OFF_W2;
    float* sW3 = sm + OFF_W3;
    float* sb1 = sm + OFF_B1;
    float* sb2 = sm + OFF_B2;
    float* sb3 = sm + OFF_B3;
    float* sF  = sm + OFF_F;
    float* sH  = sm + OFF_H;
    int*   sO  = (int*)(sm + OFF_O);

    int t = threadIdx.x;
    for (int i = t; i < FD * FH; i += ML_T) sW1[i] = W1[i];
    for (int i = t; i < FH * FH; i += ML_T) sW2[i] = W2[i];
    for (int i = t; i < FH * FO; i += ML_T) sW3[i] = W3[i];
    if (t < FH) { sb1[t] = b1[t]; sb2[t] = b2[t]; }
    if (t < FO) sb3[t] = b3[t];

    int ei = t >> 4, ci = t & 15;

    for (int c = blockIdx.x; c < MC; c += gridDim.x) {
        __syncthreads();
        if (t < FO) sO[t] = 0;
        int E = g_cnt[c];
        float cx = g_pos_s[3 * c + 0], cy = g_pos_s[3 * c + 1], cz = g_pos_s[3 * c + 2];

        {
            int e = t >> 2, q = t & 3;
            if (e < E) {
                int nb = g_nbr[c * KN + e];
                const float4* xr = (const float4*)(x + (size_t)nb * FIN);
                float4* dst = (float4*)(sF + e * FPAD + q * 16);
                dst[0] = xr[q * 4 + 0]; dst[1] = xr[q * 4 + 1];
                dst[2] = xr[q * 4 + 2]; dst[3] = xr[q * 4 + 3];
                if (q == 0) {
                    sF[e * FPAD + 64] = pos[3 * nb + 0] - cx;
                    sF[e * FPAD + 65] = pos[3 * nb + 1] - cy;
                    sF[e * FPAD + 66] = pos[3 * nb + 2] - cz;
                    sF[e * FPAD + 67] = 0.0f;
                }
            }
        }
        __syncthreads();
        int ET = (E + 3) >> 2;

        if (ei < ET) {
            float acc[4][4];
#pragma unroll
            for (int j = 0; j < 4; j++)
#pragma unroll
                for (int a = 0; a < 4; a++) acc[j][a] = sb1[ci * 4 + a];
#pragma unroll 4
            for (int k = 0; k < FD; k++) {
                float4 wv = *(const float4*)(sW1 + k * FH + ci * 4);
                float f[4];
#pragma unroll
                for (int j = 0; j < 4; j++) f[j] = sF[(4 * ei + j) * FPAD + k];
#pragma unroll
                for (int j = 0; j < 4; j++) {
                    acc[j][0] += f[j] * wv.x; acc[j][1] += f[j] * wv.y;
                    acc[j][2] += f[j] * wv.z; acc[j][3] += f[j] * wv.w;
                }
            }
#pragma unroll
            for (int j = 0; j < 4; j++)
#pragma unroll
                for (int a = 0; a < 4; a++)
                    sH[(4 * ei + j) * FPAD + ci * 4 + a] = fmaxf(acc[j][a], 0.0f);
        }
        __syncthreads();

        if (ei < ET) {
            float acc[4][4];
#pragma unroll
            for (int j = 0; j < 4; j++)
#pragma unroll
                for (int a = 0; a < 4; a++) acc[j][a] = sb2[ci * 4 + a];
#pragma unroll 4
            for (int k = 0; k < FH; k++) {
                float4 wv = *(const float4*)(sW2 + k * FH + ci * 4);
                float f[4];
#pragma unroll
                for (int j = 0; j < 4; j++) f[j] = sH[(4 * ei + j) * FPAD + k];
#pragma unroll
                for (int j = 0; j < 4; j++) {
                    acc[j][0] += f[j] * wv.x; acc[j][1] += f[j] * wv.y;
                    acc[j][2] += f[j] * wv.z; acc[j][3] += f[j] * wv.w;
                }
            }
#pragma unroll
            for (int j = 0; j < 4; j++)
#pragma unroll
                for (int a = 0; a < 4; a++)
                    sF[(4 * ei + j) * FPAD + ci * 4 + a] = fmaxf(acc[j][a], 0.0f);
        }
        __syncthreads();

        if (ei < ET) {
            float acc[4][8];
#pragma unroll
            for (int j = 0; j < 4; j++)
#pragma unroll
                for (int a = 0; a < 8; a++) acc[j][a] = sb3[ci * 8 + a];
#pragma unroll 4
            for (int k = 0; k < FH; k++) {
                float4 wa = *(const float4*)(sW3 + k * FO + ci * 8);
                float4 wb = *(const float4*)(sW3 + k * FO + ci * 8 + 4);
                float f[4];
#pragma unroll
                for (int j = 0; j < 4; j++) f[j] = sF[(4 * ei + j) * FPAD + k];
#pragma unroll
                for (int j = 0; j < 4; j++) {
                    acc[j][0] += f[j] * wa.x; acc[j][1] += f[j] * wa.y;
                    acc[j][2] += f[j] * wa.z; acc[j][3] += f[j] * wa.w;
                    acc[j][4] += f[j] * wb.x; acc[j][5] += f[j] * wb.y;
                    acc[j][6] += f[j] * wb.z; acc[j][7] += f[j] * wb.w;
                }
            }
#pragma unroll
            for (int a = 0; a < 8; a++) {
                float mv = -1.0f;
#pragma unroll
                for (int j = 0; j < 4; j++)
                    if (4 * ei + j < E) mv = fmaxf(mv, fmaxf(acc[j][a], 0.0f));
                if (mv >= 0.0f) atomicMax(&sO[ci * 8 + a], __float_as_int(mv));
            }
        }
        __syncthreads();
        if (t < FO) out[(size_t)c * FO + t] = __int_as_float(sO[t]);
    }
}

// ---------------------------------------------------------------------------
extern "C" void kernel_launch(void* const* d_in, const int* in_sizes, int n_in,
                              void* d_out, int out_size)
{
    const float* x   = (const float*)d_in[0];
    const float* pos = (const float*)d_in[1];
    const float* W1 = (const float*)d_in[3];
    const float* b1 = (const float*)d_in[4];
    const float* W2 = (const float*)d_in[5];
    const float* b2 = (const float*)d_in[6];
    const float* W3 = (const float*)d_in[7];
    const float* b3 = (const float*)d_in[8];
    float* out = (float*)d_out;

    cudaFuncSetAttribute(build_kernel, cudaFuncAttributeMaxDynamicSharedMemorySize, BLD_SMEM);
    cudaFuncSetAttribute(fps_kernel,   cudaFuncAttributeMaxDynamicSharedMemorySize, FPS_SMEM);
    cudaFuncSetAttribute(mlp_kernel,   cudaFuncAttributeMaxDynamicSharedMemorySize, ML_SMEM);

    build_kernel<<<1, BLD_T, BLD_SMEM>>>(pos);
    fps_kernel<<<1, FPS_T, FPS_SMEM>>>(pos);
    gather_kernel<<<(MC + 255) / 256, 256>>>(pos, out, out_size);
    radius_kernel<<<MC / RB_C, RB_T>>>(pos);
    mlp_kernel<<<ML_GRID, ML_T, ML_SMEM>>>(x, pos, W1, b1, W2, b2, W3, b3, out);
}

// round 15
// speedup vs baseline: 2.5205x; 1.3851x over previous
#include <cuda_runtime.h>
#include <cstdint>

typedef unsigned long long ull;

// Problem constants (fixed by the reference).
#define NP    16384
#define FIN   64
#define MC    4096
#define KN    64
#define FH    64
#define FO    128
#define FD    67
#define FPAD  68
#define R2F   0.04f

// Scratch (static __device__ — no allocations allowed).
__device__ int   g_idx[MC];
__device__ float g_pos_s[MC * 3];
__device__ int   g_nbr[MC * KN];
__device__ int   g_cnt[MC];
// Morton-reordered cloud
__device__ __align__(128) float g_px[NP];
__device__ __align__(128) float g_py[NP];
__device__ __align__(128) float g_pz[NP];
__device__ __align__(128) int   g_orig[NP];

// Packed f32x2 helpers (sm_103a): per-lane IEEE rn — bit-identical to scalar.
#define PACK2(out, lo, hi)  asm("mov.b64 %0, {%1, %2};" : "=l"(out) : "f"(lo), "f"(hi))
#define UNPACK2(lo, hi, in) asm("mov.b64 {%0, %1}, %2;" : "=f"(lo), "=f"(hi) : "l"(in))
#define ADD2(out, a, b)     asm("add.rn.f32x2 %0, %1, %2;" : "=l"(out) : "l"(a), "l"(b))
#define MUL2(out, a, b)     asm("mul.rn.f32x2 %0, %1, %2;" : "=l"(out) : "l"(a), "l"(b))
#define FMA2(out, a, b, c)  asm("fma.rn.f32x2 %0, %1, %2, %3;" : "=l"(out) : "l"(a), "l"(b), "l"(c))

// ---------------------------------------------------------------------------
// 0) Build: Morton sort (bitonic, one CTA) -> reordered coords.
// ---------------------------------------------------------------------------
__device__ __forceinline__ unsigned expand10(unsigned v) {
    v &= 1023u;
    v = (v | (v << 16)) & 0x030000FFu;
    v = (v | (v << 8))  & 0x0300F00Fu;
    v = (v | (v << 4))  & 0x030C30C3u;
    v = (v | (v << 2))  & 0x09249249u;
    return v;
}

#define BLD_T 512
#define BLD_SMEM (NP * 8)

__global__ __launch_bounds__(BLD_T) void build_kernel(const float* __restrict__ pos)
{
    extern __shared__ ull sk[];
    int t = threadIdx.x;

    for (int i = t; i < NP; i += BLD_T) {
        float x = pos[3 * i + 0], y = pos[3 * i + 1], z = pos[3 * i + 2];
        unsigned ux = (unsigned)fminf(1023.f, fmaxf(0.f, (x + 5.12f) * 100.0f));
        unsigned uy = (unsigned)fminf(1023.f, fmaxf(0.f, (y + 5.12f) * 100.0f));
        unsigned uz = (unsigned)fminf(1023.f, fmaxf(0.f, (z + 5.12f) * 100.0f));
        unsigned code = (expand10(ux) << 2) | (expand10(uy) << 1) | expand10(uz);
        sk[i] = ((ull)code << 32) | (unsigned)i;
    }
    __syncthreads();

    for (unsigned k2 = 2; k2 <= NP; k2 <<= 1) {
        for (unsigned j = k2 >> 1; j > 0; j >>= 1) {
            for (unsigned i = t; i < NP; i += BLD_T) {
                unsigned ixj = i ^ j;
                if (ixj > i) {
                    ull a = sk[i], b = sk[ixj];
                    bool up = ((i & k2) == 0);
                    if ((a > b) == up) { sk[i] = b; sk[ixj] = a; }
                }
            }
            __syncthreads();
        }
    }

    for (int i = t; i < NP; i += BLD_T) {
        unsigned idx = (unsigned)sk[i];
        g_px[i] = pos[3 * idx + 0];
        g_py[i] = pos[3 * idx + 1];
        g_pz[i] = pos[3 * idx + 2];
        g_orig[i] = (int)idx;
    }
}

// ---------------------------------------------------------------------------
// 1) FPS — single persistent CTA, 1024 threads x 16 points (R10 structure:
//    f32x2 packed update, per-lane sphere prune with whole-warp skip,
//    3-barrier selection). 2x warps vs R10 to cover exposed stalls; warp
//    spatial extent halves -> better whole-warp skip rate; thread spheres
//    shrink -> better per-lane prune. Registers budgeted for the 64-reg cap:
//    px2[8] + md[16] + sphere ~= 37 persistent, y/z via one LDS.128 per pair.
//    Skips are provably value-preserving -> bit-identical to dense FPS.
// ---------------------------------------------------------------------------
#define FPS_T 1024
#define OYZ   0
#define OOR   (OYZ + (NP / 2) * 16)
#define OMISC (OOR + NP * 2)
#define FPS_SMEM (OMISC + 256)

__global__ __launch_bounds__(FPS_T) void fps_kernel(const float* __restrict__ pos)
{
    extern __shared__ unsigned char raw[];
    float4*         s_yz  = (float4*)(raw + OYZ);          // [NP/2] (y0,y1,z0,z1)
    unsigned short* s_or  = (unsigned short*)(raw + OOR);  // [NP] transposed
    unsigned*       s_wm  = (unsigned*)(raw + OMISC);      // [32]
    unsigned*       s_win = s_wm + 32;                     // [2]
    float*          s_q   = (float*)(s_win + 2);           // [3]

    const int t = threadIdx.x, lane = t & 31, w = t >> 5;
    const int base = t * 16;
    const float INF = __int_as_float(0x7f800000);

    ull   px2[8];
    float md[16];
    float cxl = 1e30f, cxh = -1e30f, cyl = 1e30f, cyh = -1e30f,
          czl = 1e30f, czh = -1e30f;
#pragma unroll
    for (int i = 0; i < 8; i++) {
        int p = base + 2 * i;
        float x0 = g_px[p], x1 = g_px[p + 1];
        float y0 = g_py[p], y1 = g_py[p + 1];
        float z0 = g_pz[p], z1 = g_pz[p + 1];
        PACK2(px2[i], x0, x1);
        s_yz[i * FPS_T + t] = make_float4(y0, y1, z0, z1);
        s_or[(2 * i) * FPS_T + t]     = (unsigned short)g_orig[p];
        s_or[(2 * i + 1) * FPS_T + t] = (unsigned short)g_orig[p + 1];
        md[2 * i] = INF; md[2 * i + 1] = INF;
        cxl = fminf(cxl, fminf(x0, x1)); cxh = fmaxf(cxh, fmaxf(x0, x1));
        cyl = fminf(cyl, fminf(y0, y1)); cyh = fmaxf(cyh, fmaxf(y0, y1));
        czl = fminf(czl, fminf(z0, z1)); czh = fmaxf(czh, fmaxf(z0, z1));
    }
    float ccx = 0.5f * (cxl + cxh), ccy = 0.5f * (cyl + cyh), ccz = 0.5f * (czl + czh);
    float rr = 0.0f;
#pragma unroll
    for (int i = 0; i < 8; i++) {
        float x0, x1; UNPACK2(x0, x1, px2[i]);
        float4 yz = s_yz[i * FPS_T + t];
        float dx = x0 - ccx, dy = yz.x - ccy, dz = yz.z - ccz;
        rr = fmaxf(rr, dx * dx + dy * dy + dz * dz);
        dx = x1 - ccx; dy = yz.y - ccy; dz = yz.w - ccz;
        rr = fmaxf(rr, dx * dx + dy * dy + dz * dz);
    }
    float rad = __fsqrt_ru(rr) * 1.0005f + 1e-4f;
    float thr2 = INF, lanebest = INF;

    if (t == 0) {
        g_idx[0] = 0;
        s_q[0] = pos[0]; s_q[1] = pos[1]; s_q[2] = pos[2];
        s_win[0] = 0u; s_win[1] = 0u;
    }
    __syncthreads();

    for (int it = 1; it < MC; it++) {
        float qx = s_q[0], qy = s_q[1], qz = s_q[2];

        // Sphere prune: skip iff q provably can't lower any md in this thread.
        // Whole warp skips when all 32 lanes are clean (warp = 512 Morton pts).
        float ddx = qx - ccx, ddy = qy - ccy, ddz = qz - ccz;
        float d2c = ddx * ddx + ddy * ddy + ddz * ddz;
        if (d2c < thr2) {
            ull qx2, qy2, qz2;
            float nqx = -qx, nqy = -qy, nqz = -qz;
            PACK2(qx2, nqx, nqx); PACK2(qy2, nqy, nqy); PACK2(qz2, nqz, nqz);
            float best = -1.0f;
#pragma unroll
            for (int i = 0; i < 8; i++) {
                float4 yz = s_yz[i * FPS_T + t];
                ull py2, pz2, dx2, dy2, dz2, s1, d2p;
                PACK2(py2, yz.x, yz.y);
                PACK2(pz2, yz.z, yz.w);
                ADD2(dx2, px2[i], qx2);            // x - qx (rn, per lane)
                ADD2(dy2, py2, qy2);
                ADD2(dz2, pz2, qz2);
                MUL2(s1, dx2, dx2);                // dx*dx
                FMA2(s1, dy2, dy2, s1);            // fma(dy,dy,.)
                FMA2(d2p, dz2, dz2, s1);           // fma(dz,dz,.)
                float d2a, d2b; UNPACK2(d2a, d2b, d2p);
                float m0 = fminf(md[2 * i], d2a);
                float m1 = fminf(md[2 * i + 1], d2b);
                md[2 * i] = m0; md[2 * i + 1] = m1;
                best = fmaxf(best, fmaxf(m0, m1));
            }
            lanebest = best;
            float s = __fsqrt_ru(best) * 1.0005f + rad;
            thr2 = s * s;
        }

        // Selection: global max (d2>=0 -> bit order == float order).
        unsigned lb = __float_as_uint(lanebest);
        unsigned wm = __reduce_max_sync(0xFFFFFFFFu, lb);
        if (lane == 0) s_wm[w] = wm;
        __syncthreads();                                  // BAR1
        unsigned v = __reduce_max_sync(0xFFFFFFFFu, s_wm[lane]);
        int slot = it & 1;

        // Candidate threads: exact lowest-orig tie rule (atomicMax on ~orig).
        unsigned tinv = 0u; float tx = 0.0f, ty = 0.0f, tz = 0.0f;
        if (lb == v) {
#pragma unroll
            for (int m = 0; m < 16; m++) {
                if (__float_as_uint(md[m]) == v) {
                    unsigned inv = 0xFFFFFFFFu - (unsigned)s_or[m * FPS_T + t];
                    if (inv > tinv) {
                        tinv = inv;
                        float a, b; UNPACK2(a, b, px2[m >> 1]);
                        tx = (m & 1) ? b : a;
                        float4 yz = s_yz[(m >> 1) * FPS_T + t];
                        ty = (m & 1) ? yz.y : yz.x;
                        tz = (m & 1) ? yz.w : yz.z;
                    }
                }
            }
            atomicMax(&s_win[slot], tinv);
        }
        if (t == 0) s_win[slot ^ 1] = 0u;
        __syncthreads();                                  // BAR2

        unsigned win = s_win[slot];
        if (tinv != 0u && tinv == win) {                  // unique winner thread
            s_q[0] = tx; s_q[1] = ty; s_q[2] = tz;
            g_idx[it] = (int)(0xFFFFFFFFu - win);
        }
        __syncthreads();                                  // BAR3
    }
}

// ---------------------------------------------------------------------------
// 2) Gather sampled positions (+ tuple tail if flattened output).
// ---------------------------------------------------------------------------
__global__ void gather_kernel(const float* __restrict__ pos, float* __restrict__ out, int out_size)
{
    int c = blockIdx.x * blockDim.x + threadIdx.x;
    if (c >= MC) return;
    int j = g_idx[c];
    float x = pos[3 * j + 0], y = pos[3 * j + 1], z = pos[3 * j + 2];
    g_pos_s[3 * c + 0] = x; g_pos_s[3 * c + 1] = y; g_pos_s[3 * c + 2] = z;
    int base = MC * FO;
    if (out_size >= base + 3 * MC) {
        out[base + 3 * c + 0] = x; out[base + 3 * c + 1] = y; out[base + 3 * c + 2] = z;
    }
    if (out_size >= base + 4 * MC) out[base + 3 * MC + c] = 0.0f;
}

// ---------------------------------------------------------------------------
// 3) Radius neighbors (unchanged, passing).
// ---------------------------------------------------------------------------
#define RB_C   16
#define RB_T   256
#define RB_CAP 192

__global__ __launch_bounds__(RB_T) void radius_kernel(const float* __restrict__ pos)
{
    __shared__ float scx[RB_C], scy[RB_C], scz[RB_C];
    __shared__ int   scnt[RB_C];
    __shared__ int   sidx[RB_C][RB_CAP];
    __shared__ float sd2[RB_C][RB_CAP];

    int t = threadIdx.x;
    int c0 = blockIdx.x * RB_C;
    if (t < RB_C) {
        scx[t] = g_pos_s[3 * (c0 + t) + 0];
        scy[t] = g_pos_s[3 * (c0 + t) + 1];
        scz[t] = g_pos_s[3 * (c0 + t) + 2];
        scnt[t] = 0;
    }
    __syncthreads();

    for (int j = t; j < NP; j += RB_T) {
        float x = pos[3 * j + 0], y = pos[3 * j + 1], z = pos[3 * j + 2];
#pragma unroll
        for (int c = 0; c < RB_C; c++) {
            float dx = __fadd_rn(scx[c], -x);
            float dy = __fadd_rn(scy[c], -y);
            float dz = __fadd_rn(scz[c], -z);
            float d2 = __fmaf_rn(dz, dz, __fmaf_rn(dy, dy, __fmul_rn(dx, dx)));
            if (d2 <= R2F) {
                int n = atomicAdd(&scnt[c], 1);
                if (n < RB_CAP) { sidx[c][n] = j; sd2[c][n] = d2; }
            }
        }
    }
    __syncthreads();

    for (int c = 0; c < RB_C; c++) {
        int cnt = min(scnt[c], RB_CAP);
        int cg = c0 + c;
        if (cnt <= KN) {
            if (t < cnt) g_nbr[cg * KN + t] = sidx[c][t];
            if (t == 0)  g_cnt[cg] = cnt;
        } else {
            for (int i = t; i < cnt; i += RB_T) {
                float di = sd2[c][i]; int ii = sidx[c][i];
                int rank = 0;
                for (int jj = 0; jj < cnt; jj++) {
                    float dj = sd2[c][jj];
                    rank += (dj < di) || (dj == di && sidx[c][jj] < ii);
                }
                if (rank < KN) g_nbr[cg * KN + rank] = ii;
            }
            if (t == 0) g_cnt[cg] = KN;
        }
    }
}

// ---------------------------------------------------------------------------
// 4) Per-edge MLP + max-pool (unchanged, passing).
// ---------------------------------------------------------------------------
#define ML_T    256
#define ML_GRID 304

#define OFF_W1 0
#define OFF_W2 (OFF_W1 + FD * FH)
#define OFF_W3 (OFF_W2 + FH * FH)
#define OFF_B1 (OFF_W3 + FH * FO)
#define OFF_B2 (OFF_B1 + FH)
#define OFF_B3 (OFF_B2 + FH)
#define OFF_F  (OFF_B3 + FO)
#define OFF_H  (OFF_F + KN * FPAD)
#define OFF_O  (OFF_H + KN * FPAD)
#define ML_SMEM ((OFF_O + FO) * 4)

__global__ __launch_bounds__(ML_T, 2) void mlp_kernel(
    const float* __restrict__ x, const float* __restrict__ pos,
    const float* __restrict__ W1, const float* __restrict__ b1,
    const float* __restrict__ W2, const float* __restrict__ b2,
    const float* __restrict__ W3, const float* __restrict__ b3,
    float* __restrict__ out)
{
    extern __shared__ float sm[];
    float* sW1 = sm + OFF_W1;
    float* sW2 = sm + OFF_W2;
    float* sW3 = sm + OFF_W3;
    float* sb1 = sm + OFF_B1;
    float* sb2 = sm + OFF_B2;
    float* sb3 = sm + OFF_B3;
    float* sF  = sm + OFF_F;
    float* sH  = sm + OFF_H;
    int*   sO  = (int*)(sm + OFF_O);

    int t = threadIdx.x;
    for (int i = t; i < FD * FH; i += ML_T) sW1[i] = W1[i];
    for (int i = t; i < FH * FH; i += ML_T) sW2[i] = W2[i];
    for (int i = t; i < FH * FO; i += ML_T) sW3[i] = W3[i];
    if (t < FH) { sb1[t] = b1[t]; sb2[t] = b2[t]; }
    if (t < FO) sb3[t] = b3[t];

    int ei = t >> 4, ci = t & 15;

    for (int c = blockIdx.x; c < MC; c += gridDim.x) {
        __syncthreads();
        if (t < FO) sO[t] = 0;
        int E = g_cnt[c];
        float cx = g_pos_s[3 * c + 0], cy = g_pos_s[3 * c + 1], cz = g_pos_s[3 * c + 2];

        {
            int e = t >> 2, q = t & 3;
            if (e < E) {
                int nb = g_nbr[c * KN + e];
                const float4* xr = (const float4*)(x + (size_t)nb * FIN);
                float4* dst = (float4*)(sF + e * FPAD + q * 16);
                dst[0] = xr[q * 4 + 0]; dst[1] = xr[q * 4 + 1];
                dst[2] = xr[q * 4 + 2]; dst[3] = xr[q * 4 + 3];
                if (q == 0) {
                    sF[e * FPAD + 64] = pos[3 * nb + 0] - cx;
                    sF[e * FPAD + 65] = pos[3 * nb + 1] - cy;
                    sF[e * FPAD + 66] = pos[3 * nb + 2] - cz;
                    sF[e * FPAD + 67] = 0.0f;
                }
            }
        }
        __syncthreads();
        int ET = (E + 3) >> 2;

        if (ei < ET) {
            float acc[4][4];
#pragma unroll
            for (int j = 0; j < 4; j++)
#pragma unroll
                for (int a = 0; a < 4; a++) acc[j][a] = sb1[ci * 4 + a];
#pragma unroll 4
            for (int k = 0; k < FD; k++) {
                float4 wv = *(const float4*)(sW1 + k * FH + ci * 4);
                float f[4];
#pragma unroll
                for (int j = 0; j < 4; j++) f[j] = sF[(4 * ei + j) * FPAD + k];
#pragma unroll
                for (int j = 0; j < 4; j++) {
                    acc[j][0] += f[j] * wv.x; acc[j][1] += f[j] * wv.y;
                    acc[j][2] += f[j] * wv.z; acc[j][3] += f[j] * wv.w;
                }
            }
#pragma unroll
            for (int j = 0; j < 4; j++)
#pragma unroll
                for (int a = 0; a < 4; a++)
                    sH[(4 * ei + j) * FPAD + ci * 4 + a] = fmaxf(acc[j][a], 0.0f);
        }
        __syncthreads();

        if (ei < ET) {
            float acc[4][4];
#pragma unroll
            for (int j = 0; j < 4; j++)
#pragma unroll
                for (int a = 0; a < 4; a++) acc[j][a] = sb2[ci * 4 + a];
#pragma unroll 4
            for (int k = 0; k < FH; k++) {
                float4 wv = *(const float4*)(sW2 + k * FH + ci * 4);
                float f[4];
#pragma unroll
                for (int j = 0; j < 4; j++) f[j] = sH[(4 * ei + j) * FPAD + k];
#pragma unroll
                for (int j = 0; j < 4; j++) {
                    acc[j][0] += f[j] * wv.x; acc[j][1] += f[j] * wv.y;
                    acc[j][2] += f[j] * wv.z; acc[j][3] += f[j] * wv.w;
                }
            }
#pragma unroll
            for (int j = 0; j < 4; j++)
#pragma unroll
                for (int a = 0; a < 4; a++)
                    sF[(4 * ei + j) * FPAD + ci * 4 + a] = fmaxf(acc[j][a], 0.0f);
        }
        __syncthreads();

        if (ei < ET) {
            float acc[4][8];
#pragma unroll
            for (int j = 0; j < 4; j++)
#pragma unroll
                for (int a = 0; a < 8; a++) acc[j][a] = sb3[ci * 8 + a];
#pragma unroll 4
            for (int k = 0; k < FH; k++) {
                float4 wa = *(const float4*)(sW3 + k * FO + ci * 8);
                float4 wb = *(const float4*)(sW3 + k * FO + ci * 8 + 4);
                float f[4];
#pragma unroll
                for (int j = 0; j < 4; j++) f[j] = sF[(4 * ei + j) * FPAD + k];
#pragma unroll
                for (int j = 0; j < 4; j++) {
                    acc[j][0] += f[j] * wa.x; acc[j][1] += f[j] * wa.y;
                    acc[j][2] += f[j] * wa.z; acc[j][3] += f[j] * wa.w;
                    acc[j][4] += f[j] * wb.x; acc[j][5] += f[j] * wb.y;
                    acc[j][6] += f[j] * wb.z; acc[j][7] += f[j] * wb.w;
                }
            }
#pragma unroll
            for (int a = 0; a < 8; a++) {
                float mv = -1.0f;
#pragma unroll
                for (int j = 0; j < 4; j++)
                    if (4 * ei + j < E) mv = fmaxf(mv, fmaxf(acc[j][a], 0.0f));
                if (mv >= 0.0f) atomicMax(&sO[ci * 8 + a], __float_as_int(mv));
            }
        }
        __syncthreads();
        if (t < FO) out[(size_t)c * FO + t] = __int_as_float(sO[t]);
    }
}

// ---------------------------------------------------------------------------
extern "C" void kernel_launch(void* const* d_in, const int* in_sizes, int n_in,
                              void* d_out, int out_size)
{
    const float* x   = (const float*)d_in[0];
    const float* pos = (const float*)d_in[1];
    const float* W1 = (const float*)d_in[3];
    const float* b1 = (const float*)d_in[4];
    const float* W2 = (const float*)d_in[5];
    const float* b2 = (const float*)d_in[6];
    const float* W3 = (const float*)d_in[7];
    const float* b3 = (const float*)d_in[8];
    float* out = (float*)d_out;

    cudaFuncSetAttribute(build_kernel, cudaFuncAttributeMaxDynamicSharedMemorySize, BLD_SMEM);
    cudaFuncSetAttribute(fps_kernel,   cudaFuncAttributeMaxDynamicSharedMemorySize, FPS_SMEM);
    cudaFuncSetAttribute(mlp_kernel,   cudaFuncAttributeMaxDynamicSharedMemorySize, ML_SMEM);

    build_kernel<<<1, BLD_T, BLD_SMEM>>>(pos);
    fps_kernel<<<1, FPS_T, FPS_SMEM>>>(pos);
    gather_kernel<<<(MC + 255) / 256, 256>>>(pos, out, out_size);
    radius_kernel<<<MC / RB_C, RB_T>>>(pos);
    mlp_kernel<<<ML_GRID, ML_T, ML_SMEM>>>(x, pos, W1, b1, W2, b2, W3, b3, out);
}

// round 17
// speedup vs baseline: 2.9422x; 1.1673x over previous
#include <cuda_runtime.h>
#include <cstdint>

typedef unsigned long long ull;

// Problem constants (fixed by the reference).
#define NP    16384
#define FIN   64
#define MC    4096
#define KN    64
#define FH    64
#define FO    128
#define FD    67
#define FPAD  68
#define R2F   0.04f

// Scratch (static __device__ — no allocations allowed).
__device__ int   g_idx[MC];
__device__ float g_pos_s[MC * 3];
__device__ int   g_nbr[MC * KN];
__device__ int   g_cnt[MC];
// Morton-reordered cloud
__device__ __align__(128) float g_px[NP];
__device__ __align__(128) float g_py[NP];
__device__ __align__(128) float g_pz[NP];
__device__ __align__(128) int   g_orig[NP];

// Packed f32x2 helpers (sm_103a): per-lane IEEE rn — bit-identical to scalar.
#define PACK2(out, lo, hi)  asm("mov.b64 %0, {%1, %2};" : "=l"(out) : "f"(lo), "f"(hi))
#define UNPACK2(lo, hi, in) asm("mov.b64 {%0, %1}, %2;" : "=f"(lo), "=f"(hi) : "l"(in))
#define ADD2(out, a, b)     asm("add.rn.f32x2 %0, %1, %2;" : "=l"(out) : "l"(a), "l"(b))
#define MUL2(out, a, b)     asm("mul.rn.f32x2 %0, %1, %2;" : "=l"(out) : "l"(a), "l"(b))
#define FMA2(out, a, b, c)  asm("fma.rn.f32x2 %0, %1, %2, %3;" : "=l"(out) : "l"(a), "l"(b), "l"(c))

// ---------------------------------------------------------------------------
// 0) Build: Morton sort (bitonic, one CTA) -> reordered coords.
// ---------------------------------------------------------------------------
__device__ __forceinline__ unsigned expand10(unsigned v) {
    v &= 1023u;
    v = (v | (v << 16)) & 0x030000FFu;
    v = (v | (v << 8))  & 0x0300F00Fu;
    v = (v | (v << 4))  & 0x030C30C3u;
    v = (v | (v << 2))  & 0x09249249u;
    return v;
}

#define BLD_T 512
#define BLD_SMEM (NP * 8)

__global__ __launch_bounds__(BLD_T) void build_kernel(const float* __restrict__ pos)
{
    extern __shared__ ull sk[];
    int t = threadIdx.x;

    for (int i = t; i < NP; i += BLD_T) {
        float x = pos[3 * i + 0], y = pos[3 * i + 1], z = pos[3 * i + 2];
        unsigned ux = (unsigned)fminf(1023.f, fmaxf(0.f, (x + 5.12f) * 100.0f));
        unsigned uy = (unsigned)fminf(1023.f, fmaxf(0.f, (y + 5.12f) * 100.0f));
        unsigned uz = (unsigned)fminf(1023.f, fmaxf(0.f, (z + 5.12f) * 100.0f));
        unsigned code = (expand10(ux) << 2) | (expand10(uy) << 1) | expand10(uz);
        sk[i] = ((ull)code << 32) | (unsigned)i;
    }
    __syncthreads();

    for (unsigned k2 = 2; k2 <= NP; k2 <<= 1) {
        for (unsigned j = k2 >> 1; j > 0; j >>= 1) {
            for (unsigned i = t; i < NP; i += BLD_T) {
                unsigned ixj = i ^ j;
                if (ixj > i) {
                    ull a = sk[i], b = sk[ixj];
                    bool up = ((i & k2) == 0);
                    if ((a > b) == up) { sk[i] = b; sk[ixj] = a; }
                }
            }
            __syncthreads();
        }
    }

    for (int i = t; i < NP; i += BLD_T) {
        unsigned idx = (unsigned)sk[i];
        g_px[i] = pos[3 * idx + 0];
        g_py[i] = pos[3 * idx + 1];
        g_pz[i] = pos[3 * idx + 2];
        g_orig[i] = (int)idx;
    }
}

// ---------------------------------------------------------------------------
// 1) FPS — single persistent CTA, 1024 threads x 16 points (R15 structure,
//    proven best) with a TWO-barrier selection:
//    candidates atomicMax a packed key ((16384-orig)<<14 | morton); after
//    BAR2 every thread decodes morton and fetches q itself via broadcast
//    LDS from smem (x mirrored to smem for this). q lives in registers;
//    the winner-publish round-trip and BAR3 are gone.
//    Skips are provably value-preserving -> bit-identical to dense FPS.
// ---------------------------------------------------------------------------
#define FPS_T 1024
#define OX2   0
#define OYZ   (OX2 + (NP / 2) * 8)
#define OOR   (OYZ + (NP / 2) * 16)
#define OMISC (OOR + NP * 2)
#define FPS_SMEM (OMISC + 256)

__global__ __launch_bounds__(FPS_T) void fps_kernel(const float* __restrict__ pos)
{
    extern __shared__ unsigned char raw[];
    float2*         s_x2  = (float2*)(raw + OX2);          // [NP/2] (x0,x1)
    float4*         s_yz  = (float4*)(raw + OYZ);          // [NP/2] (y0,y1,z0,z1)
    unsigned short* s_or  = (unsigned short*)(raw + OOR);  // [NP] transposed
    unsigned*       s_wm  = (unsigned*)(raw + OMISC);      // [32]
    unsigned*       s_win = s_wm + 32;                     // [2]

    const int t = threadIdx.x, lane = t & 31, w = t >> 5;
    const int base = t * 16;
    const float INF = __int_as_float(0x7f800000);

    ull   px2[8];
    float md[16];
    float cxl = 1e30f, cxh = -1e30f, cyl = 1e30f, cyh = -1e30f,
          czl = 1e30f, czh = -1e30f;
#pragma unroll
    for (int i = 0; i < 8; i++) {
        int p = base + 2 * i;
        float x0 = g_px[p], x1 = g_px[p + 1];
        float y0 = g_py[p], y1 = g_py[p + 1];
        float z0 = g_pz[p], z1 = g_pz[p + 1];
        PACK2(px2[i], x0, x1);
        s_x2[i * FPS_T + t] = make_float2(x0, x1);
        s_yz[i * FPS_T + t] = make_float4(y0, y1, z0, z1);
        s_or[(2 * i) * FPS_T + t]     = (unsigned short)g_orig[p];
        s_or[(2 * i + 1) * FPS_T + t] = (unsigned short)g_orig[p + 1];
        md[2 * i] = INF; md[2 * i + 1] = INF;
        cxl = fminf(cxl, fminf(x0, x1)); cxh = fmaxf(cxh, fmaxf(x0, x1));
        cyl = fminf(cyl, fminf(y0, y1)); cyh = fmaxf(cyh, fmaxf(y0, y1));
        czl = fminf(czl, fminf(z0, z1)); czh = fmaxf(czh, fmaxf(z0, z1));
    }
    float ccx = 0.5f * (cxl + cxh), ccy = 0.5f * (cyl + cyh), ccz = 0.5f * (czl + czh);
    float rr = 0.0f;
#pragma unroll
    for (int i = 0; i < 8; i++) {
        float x0, x1; UNPACK2(x0, x1, px2[i]);
        float4 yz = s_yz[i * FPS_T + t];
        float dx = x0 - ccx, dy = yz.x - ccy, dz = yz.z - ccz;
        rr = fmaxf(rr, dx * dx + dy * dy + dz * dz);
        dx = x1 - ccx; dy = yz.y - ccy; dz = yz.w - ccz;
        rr = fmaxf(rr, dx * dx + dy * dy + dz * dz);
    }
    float rad = __fsqrt_ru(rr) * 1.0005f + 1e-4f;
    float thr2 = INF, lanebest = INF;

    // q carried in registers by every thread (broadcast LDG at init).
    float qx = pos[0], qy = pos[1], qz = pos[2];
    if (t == 0) {
        g_idx[0] = 0;
        s_win[0] = 0u; s_win[1] = 0u;
    }
    __syncthreads();

    for (int it = 1; it < MC; it++) {
        // Sphere prune: skip iff q provably can't lower any md in this thread.
        // Whole warp skips when all 32 lanes are clean (warp = 512 Morton pts).
        float ddx = qx - ccx, ddy = qy - ccy, ddz = qz - ccz;
        float d2c = ddx * ddx + ddy * ddy + ddz * ddz;
        if (d2c < thr2) {
            ull qx2, qy2, qz2;
            float nqx = -qx, nqy = -qy, nqz = -qz;
            PACK2(qx2, nqx, nqx); PACK2(qy2, nqy, nqy); PACK2(qz2, nqz, nqz);
            float best = -1.0f;
#pragma unroll
            for (int i = 0; i < 8; i++) {
                float4 yz = s_yz[i * FPS_T + t];
                ull py2, pz2, dx2, dy2, dz2, s1, d2p;
                PACK2(py2, yz.x, yz.y);
                PACK2(pz2, yz.z, yz.w);
                ADD2(dx2, px2[i], qx2);            // x - qx (rn, per lane)
                ADD2(dy2, py2, qy2);
                ADD2(dz2, pz2, qz2);
                MUL2(s1, dx2, dx2);                // dx*dx
                FMA2(s1, dy2, dy2, s1);            // fma(dy,dy,.)
                FMA2(d2p, dz2, dz2, s1);           // fma(dz,dz,.)
                float d2a, d2b; UNPACK2(d2a, d2b, d2p);
                float m0 = fminf(md[2 * i], d2a);
                float m1 = fminf(md[2 * i + 1], d2b);
                md[2 * i] = m0; md[2 * i + 1] = m1;
                best = fmaxf(best, fmaxf(m0, m1));
            }
            lanebest = best;
            float s = __fsqrt_ru(best) * 1.0005f + rad;
            thr2 = s * s;
        }

        // Selection (2 barriers): global max (d2>=0 -> bit order == float order).
        unsigned lb = __float_as_uint(lanebest);
        unsigned wm = __reduce_max_sync(0xFFFFFFFFu, lb);
        if (lane == 0) s_wm[w] = wm;
        __syncthreads();                                  // BAR1
        unsigned v = __reduce_max_sync(0xFFFFFFFFu, s_wm[lane]);
        int slot = it & 1;

        // Candidates: packed key = (16384-orig)<<14 | morton (orig unique ->
        // max key == lowest orig; key > 0 always, so 0 is a safe sentinel).
        if (lb == v) {
            unsigned bestkey = 0u;
#pragma unroll
            for (int m = 0; m < 16; m++) {
                if (__float_as_uint(md[m]) == v) {
                    unsigned orig = (unsigned)s_or[m * FPS_T + t];
                    unsigned key = ((16384u - orig) << 14) | (unsigned)(base + m);
                    if (key > bestkey) bestkey = key;
                }
            }
            if (bestkey) atomicMax(&s_win[slot], bestkey);
        }
        if (t == 0) s_win[slot ^ 1] = 0u;   // prior readers fenced by BAR1
        __syncthreads();                                  // BAR2

        // Every thread decodes the winner and fetches q itself (broadcast LDS).
        unsigned win = s_win[slot];
        int morton = (int)(win & 16383u);
        int oi = (morton & 15) >> 1;                       // pair slot 0..7
        int ot = morton >> 4;                              // owner thread
        float2 x2 = s_x2[oi * FPS_T + ot];
        float4 yz = s_yz[oi * FPS_T + ot];
        if (morton & 1) { qx = x2.y; qy = yz.y; qz = yz.w; }
        else            { qx = x2.x; qy = yz.x; qz = yz.z; }
        if (t == 0) g_idx[it] = (int)(16384u - (win >> 14));
    }
}

// ---------------------------------------------------------------------------
// 2) Gather sampled positions (+ tuple tail if flattened output).
// ---------------------------------------------------------------------------
__global__ void gather_kernel(const float* __restrict__ pos, float* __restrict__ out, int out_size)
{
    int c = blockIdx.x * blockDim.x + threadIdx.x;
    if (c >= MC) return;
    int j = g_idx[c];
    float x = pos[3 * j + 0], y = pos[3 * j + 1], z = pos[3 * j + 2];
    g_pos_s[3 * c + 0] = x; g_pos_s[3 * c + 1] = y; g_pos_s[3 * c + 2] = z;
    int base = MC * FO;
    if (out_size >= base + 3 * MC) {
        out[base + 3 * c + 0] = x; out[base + 3 * c + 1] = y; out[base + 3 * c + 2] = z;
    }
    if (out_size >= base + 4 * MC) out[base + 3 * MC + c] = 0.0f;
}

// ---------------------------------------------------------------------------
// 3) Radius neighbors (unchanged, passing).
// ---------------------------------------------------------------------------
#define RB_C   16
#define RB_T   256
#define RB_CAP 192

__global__ __launch_bounds__(RB_T) void radius_kernel(const float* __restrict__ pos)
{
    __shared__ float scx[RB_C], scy[RB_C], scz[RB_C];
    __shared__ int   scnt[RB_C];
    __shared__ int   sidx[RB_C][RB_CAP];
    __shared__ float sd2[RB_C][RB_CAP];

    int t = threadIdx.x;
    int c0 = blockIdx.x * RB_C;
    if (t < RB_C) {
        scx[t] = g_pos_s[3 * (c0 + t) + 0];
        scy[t] = g_pos_s[3 * (c0 + t) + 1];
        scz[t] = g_pos_s[3 * (c0 + t) + 2];
        scnt[t] = 0;
    }
    __syncthreads();

    for (int j = t; j < NP; j += RB_T) {
        float x = pos[3 * j + 0], y = pos[3 * j + 1], z = pos[3 * j + 2];
#pragma unroll
        for (int c = 0; c < RB_C; c++) {
            float dx = __fadd_rn(scx[c], -x);
            float dy = __fadd_rn(scy[c], -y);
            float dz = __fadd_rn(scz[c], -z);
            float d2 = __fmaf_rn(dz, dz, __fmaf_rn(dy, dy, __fmul_rn(dx, dx)));
            if (d2 <= R2F) {
                int n = atomicAdd(&scnt[c], 1);
                if (n < RB_CAP) { sidx[c][n] = j; sd2[c][n] = d2; }
            }
        }
    }
    __syncthreads();

    for (int c = 0; c < RB_C; c++) {
        int cnt = min(scnt[c], RB_CAP);
        int cg = c0 + c;
        if (cnt <= KN) {
            if (t < cnt) g_nbr[cg * KN + t] = sidx[c][t];
            if (t == 0)  g_cnt[cg] = cnt;
        } else {
            for (int i = t; i < cnt; i += RB_T) {
                float di = sd2[c][i]; int ii = sidx[c][i];
                int rank = 0;
                for (int jj = 0; jj < cnt; jj++) {
                    float dj = sd2[c][jj];
                    rank += (dj < di) || (dj == di && sidx[c][jj] < ii);
                }
                if (rank < KN) g_nbr[cg * KN + rank] = ii;
            }
            if (t == 0) g_cnt[cg] = KN;
        }
    }
}

// ---------------------------------------------------------------------------
// 4) Per-edge MLP + max-pool (unchanged, passing).
// ---------------------------------------------------------------------------
#define ML_T    256
#define ML_GRID 304

#define OFF_W1 0
#define OFF_W2 (OFF_W1 + FD * FH)
#define OFF_W3 (OFF_W2 + FH * FH)
#define OFF_B1 (OFF_W3 + FH * FO)
#define OFF_B2 (OFF_B1 + FH)
#define OFF_B3 (OFF_B2 + FH)
#define OFF_F  (OFF_B3 + FO)
#define OFF_H  (OFF_F + KN * FPAD)
#define OFF_O  (OFF_H + KN * FPAD)
#define ML_SMEM ((OFF_O + FO) * 4)

__global__ __launch_bounds__(ML_T, 2) void mlp_kernel(
    const float* __restrict__ x, const float* __restrict__ pos,
    const float* __restrict__ W1, const float* __restrict__ b1,
    const float* __restrict__ W2, const float* __restrict__ b2,
    const float* __restrict__ W3, const float* __restrict__ b3,
    float* __restrict__ out)
{
    extern __shared__ float sm[];
    float* sW1 = sm + OFF_W1;
    float* sW2 = sm + OFF_W2;
    float* sW3 = sm + OFF_W3;
    float* sb1 = sm + OFF_B1;
    float* sb2 = sm + OFF_B2;
    float* sb3 = sm + OFF_B3;
    float* sF  = sm + OFF_F;
    float* sH  = sm + OFF_H;
    int*   sO  = (int*)(sm + OFF_O);

    int t = threadIdx.x;
    for (int i = t; i < FD * FH; i += ML_T) sW1[i] = W1[i];
    for (int i = t; i < FH * FH; i += ML_T) sW2[i] = W2[i];
    for (int i = t; i < FH * FO; i += ML_T) sW3[i] = W3[i];
    if (t < FH) { sb1[t] = b1[t]; sb2[t] = b2[t]; }
    if (t < FO) sb3[t] = b3[t];

    int ei = t >> 4, ci = t & 15;

    for (int c = blockIdx.x; c < MC; c += gridDim.x) {
        __syncthreads();
        if (t < FO) sO[t] = 0;
        int E = g_cnt[c];
        float cx = g_pos_s[3 * c + 0], cy = g_pos_s[3 * c + 1], cz = g_pos_s[3 * c + 2];

        {
            int e = t >> 2, q = t & 3;
            if (e < E) {
                int nb = g_nbr[c * KN + e];
                const float4* xr = (const float4*)(x + (size_t)nb * FIN);
                float4* dst = (float4*)(sF + e * FPAD + q * 16);
                dst[0] = xr[q * 4 + 0]; dst[1] = xr[q * 4 + 1];
                dst[2] = xr[q * 4 + 2]; dst[3] = xr[q * 4 + 3];
                if (q == 0) {
                    sF[e * FPAD + 64] = pos[3 * nb + 0] - cx;
                    sF[e * FPAD + 65] = pos[3 * nb + 1] - cy;
                    sF[e * FPAD + 66] = pos[3 * nb + 2] - cz;
                    sF[e * FPAD + 67] = 0.0f;
                }
            }
        }
        __syncthreads();
        int ET = (E + 3) >> 2;

        if (ei < ET) {
            float acc[4][4];
#pragma unroll
            for (int j = 0; j < 4; j++)
#pragma unroll
                for (int a = 0; a < 4; a++) acc[j][a] = sb1[ci * 4 + a];
#pragma unroll 4
            for (int k = 0; k < FD; k++) {
                float4 wv = *(const float4*)(sW1 + k * FH + ci * 4);
                float f[4];
#pragma unroll
                for (int j = 0; j < 4; j++) f[j] = sF[(4 * ei + j) * FPAD + k];
#pragma unroll
                for (int j = 0; j < 4; j++) {
                    acc[j][0] += f[j] * wv.x; acc[j][1] += f[j] * wv.y;
                    acc[j][2] += f[j] * wv.z; acc[j][3] += f[j] * wv.w;
                }
            }
#pragma unroll
            for (int j = 0; j < 4; j++)
#pragma unroll
                for (int a = 0; a < 4; a++)
                    sH[(4 * ei + j) * FPAD + ci * 4 + a] = fmaxf(acc[j][a], 0.0f);
        }
        __syncthreads();

        if (ei < ET) {
            float acc[4][4];
#pragma unroll
            for (int j = 0; j < 4; j++)
#pragma unroll
                for (int a = 0; a < 4; a++) acc[j][a] = sb2[ci * 4 + a];
#pragma unroll 4
            for (int k = 0; k < FH; k++) {
                float4 wv = *(const float4*)(sW2 + k * FH + ci * 4);
                float f[4];
#pragma unroll
                for (int j = 0; j < 4; j++) f[j] = sH[(4 * ei + j) * FPAD + k];
#pragma unroll
                for (int j = 0; j < 4; j++) {
                    acc[j][0] += f[j] * wv.x; acc[j][1] += f[j] * wv.y;
                    acc[j][2] += f[j] * wv.z; acc[j][3] += f[j] * wv.w;
                }
            }
#pragma unroll
            for (int j = 0; j < 4; j++)
#pragma unroll
                for (int a = 0; a < 4; a++)
                    sF[(4 * ei + j) * FPAD + ci * 4 + a] = fmaxf(acc[j][a], 0.0f);
        }
        __syncthreads();

        if (ei < ET) {
            float acc[4][8];
#pragma unroll
            for (int j = 0; j < 4; j++)
#pragma unroll
                for (int a = 0; a < 8; a++) acc[j][a] = sb3[ci * 8 + a];
#pragma unroll 4
            for (int k = 0; k < FH; k++) {
                float4 wa = *(const float4*)(sW3 + k * FO + ci * 8);
                float4 wb = *(const float4*)(sW3 + k * FO + ci * 8 + 4);
                float f[4];
#pragma unroll
                for (int j = 0; j < 4; j++) f[j] = sF[(4 * ei + j) * FPAD + k];
#pragma unroll
                for (int j = 0; j < 4; j++) {
                    acc[j][0] += f[j] * wa.x; acc[j][1] += f[j] * wa.y;
                    acc[j][2] += f[j] * wa.z; acc[j][3] += f[j] * wa.w;
                    acc[j][4] += f[j] * wb.x; acc[j][5] += f[j] * wb.y;
                    acc[j][6] += f[j] * wb.z; acc[j][7] += f[j] * wb.w;
                }
            }
#pragma unroll
            for (int a = 0; a < 8; a++) {
                float mv = -1.0f;
#pragma unroll
                for (int j = 0; j < 4; j++)
                    if (4 * ei + j < E) mv = fmaxf(mv, fmaxf(acc[j][a], 0.0f));
                if (mv >= 0.0f) atomicMax(&sO[ci * 8 + a], __float_as_int(mv));
            }
        }
        __syncthreads();
        if (t < FO) out[(size_t)c * FO + t] = __int_as_float(sO[t]);
    }
}

// ---------------------------------------------------------------------------
extern "C" void kernel_launch(void* const* d_in, const int* in_sizes, int n_in,
                              void* d_out, int out_size)
{
    const float* x   = (const float*)d_in[0];
    const float* pos = (const float*)d_in[1];
    const float* W1 = (const float*)d_in[3];
    const float* b1 = (const float*)d_in[4];
    const float* W2 = (const float*)d_in[5];
    const float* b2 = (const float*)d_in[6];
    const float* W3 = (const float*)d_in[7];
    const float* b3 = (const float*)d_in[8];
    float* out = (float*)d_out;

    cudaFuncSetAttribute(build_kernel, cudaFuncAttributeMaxDynamicSharedMemorySize, BLD_SMEM);
    cudaFuncSetAttribute(fps_kernel,   cudaFuncAttributeMaxDynamicSharedMemorySize, FPS_SMEM);
    cudaFuncSetAttribute(mlp_kernel,   cudaFuncAttributeMaxDynamicSharedMemorySize, ML_SMEM);

    build_kernel<<<1, BLD_T, BLD_SMEM>>>(pos);
    fps_kernel<<<1, FPS_T, FPS_SMEM>>>(pos);
    gather_kernel<<<(MC + 255) / 256, 256>>>(pos, out, out_size);
    radius_kernel<<<MC / RB_C, RB_T>>>(pos);
    mlp_kernel<<<ML_GRID, ML_T, ML_SMEM>>>(x, pos, W1, b1, W2, b2, W3, b3, out);
}